// round 10
// baseline (speedup 1.0000x reference)
#include <cuda_runtime.h>
#include <math.h>

#define NB 512
#define FDIM 4096
#define DEG 3
#define NTHREADS 512
#define BATCH 8192
#define PSTRIDE 5632             // per-degree perm stride (u16), lists padded to 4
#define NGROUPS (BATCH / 4)      // 2048 groups of 4 rows
#define GRID_MAIN 296            // 148 SMs x 2 CTAs

// CSR of inverted hash tables (built once per launch, deterministic).
// perm entry (u16): PRE-SWIZZLED feature (13 bits; swizzle f^((f>>4)&3),
// 4096 = zero-pad slot) | sign<<15 (1 -> +x). Offsets in uint2 (4-entry) units.
__device__ __align__(16) unsigned short g_perm[DEG * PSTRIDE];
__device__ __align__(16) unsigned short g_off[DEG * (NB + 1)];
__device__ unsigned g_ctr;

// ---------------------------------------------------------------------------
// Prologue: one block per degree. 16 chunks of 256 features, chunk-major
// stable ordering, in-warp rank via __match_any. Lists padded to 4 u16.
// ---------------------------------------------------------------------------
__global__ void __launch_bounds__(NTHREADS)
build_csr(const int* __restrict__ idxh, const int* __restrict__ bith)
{
    __shared__ int hist[16][NB];
    __shared__ int tot[NB];
    __shared__ int sc[2][NB];
    const int t = threadIdx.x;
    const int d = blockIdx.x;
    const int w = t >> 5, lane = t & 31;

    if (d == 0 && t == 0) g_ctr = 0;    // reset persistent-work counter

    for (int i = t; i < 16 * NB; i += NTHREADS) ((int*)hist)[i] = 0;
    __syncthreads();

    {   // chunk w = features [256w, 256w+256)
        const int base = d * FDIM + w * 256;
        for (int it = 0; it < 8; it++) {
            int b = idxh[base + it * 32 + lane];
            atomicAdd(&hist[w][b], 1);
        }
    }
    __syncthreads();

    // prefill pads (f=4096 -> zero slot, sign 0)
    for (int i = t; i < PSTRIDE; i += NTHREADS) g_perm[d * PSTRIDE + i] = 0x1000;

    {   // totals, padded to multiple of 4
        int c = 0;
        #pragma unroll
        for (int ch = 0; ch < 16; ch++) c += hist[ch][t];
        tot[t] = (c + 3) & ~3;
    }
    __syncthreads();
    int* s = sc[0]; int* dd = sc[1];
    s[t] = tot[t]; __syncthreads();
    for (int off = 1; off < NB; off <<= 1) {
        int v = s[t];
        if (t >= off) v += s[t - off];
        dd[t] = v;
        int* tmp = s; s = dd; dd = tmp;
        __syncthreads();
    }
    const int excl = (t == 0) ? 0 : s[t - 1];
    g_off[d * (NB + 1) + t] = (unsigned short)(excl >> 2);
    if (t == NB - 1) g_off[d * (NB + 1) + NB] = (unsigned short)(s[NB - 1] >> 2);
    {   // per-chunk cursors (element granularity)
        int base = excl;
        #pragma unroll
        for (int c = 0; c < 16; c++) {
            int h = hist[c][t];
            hist[c][t] = base;
            base += h;
        }
    }
    __syncthreads();

    {   // stable scatter, chunk w; store PRE-SWIZZLED feature index
        const int fbase = w * 256;
        for (int it = 0; it < 8; it++) {
            int f  = fbase + it * 32 + lane;
            int b  = idxh[d * FDIM + f];
            int sg = bith[d * FDIM + f];
            int fs = f ^ ((f >> 4) & 3);          // staging swizzle (bits 0-1)
            unsigned m = __match_any_sync(0xffffffffu, b);
            int rank = __popc(m & ((1u << lane) - 1));
            int grp  = __popc(m);
            int base = hist[w][b];
            g_perm[d * PSTRIDE + base + rank] = (unsigned short)(fs | (sg << 15));
            if (rank == grp - 1) hist[w][b] = base + grp;
            __syncwarp();
        }
    }
}

// ---------------------------------------------------------------------------
// float2 (complex) radix-8 pieces. Swizzle phi(m) = m ^ (((m>>4)&7) |
// (((m>>6)&1)<<3)) is conflict-free for all load/store patterns used.
// ---------------------------------------------------------------------------
__device__ __forceinline__ int phi(int m) {
    return m ^ (((m >> 4) & 7) | (((m >> 6) & 1) << 3));
}

__device__ __forceinline__ void r8_butterfly(const float* ar, const float* ai,
                                             float* Xr, float* Xi)
{
    float b0r=ar[0]+ar[4], b0i=ai[0]+ai[4];
    float b4r=ar[0]-ar[4], b4i=ai[0]-ai[4];
    float b1r=ar[1]+ar[5], b1i=ai[1]+ai[5];
    float b5r=ar[1]-ar[5], b5i=ai[1]-ai[5];
    float b2r=ar[2]+ar[6], b2i=ai[2]+ai[6];
    float b6r=ar[2]-ar[6], b6i=ai[2]-ai[6];
    float b3r=ar[3]+ar[7], b3i=ai[3]+ai[7];
    float b7r=ar[3]-ar[7], b7i=ai[3]-ai[7];
    float c0r=b0r+b2r, c0i=b0i+b2i;
    float c2r=b0r-b2r, c2i=b0i-b2i;
    float c1r=b1r+b3r, c1i=b1i+b3i;
    float c3r=b1r-b3r, c3i=b1i-b3i;
    float c4r=b4r+b6i, c4i=b4i-b6r;
    float c6r=b4r-b6i, c6i=b4i+b6r;
    float c5r=b5r+b7i, c5i=b5i-b7r;
    float c7r=b5r-b7i, c7i=b5i+b7r;
    Xr[0]=c0r+c1r; Xi[0]=c0i+c1i;
    Xr[4]=c0r-c1r; Xi[4]=c0i-c1i;
    Xr[2]=c2r+c3i; Xi[2]=c2i-c3r;
    Xr[6]=c2r-c3i; Xi[6]=c2i+c3r;
    const float R2 = 0.70710678118654752440f;
    const float u5r=(c5r+c5i)*R2, u5i=(c5i-c5r)*R2;        // w8^1 * c5
    Xr[1]=c4r+u5r; Xi[1]=c4i+u5i;
    Xr[5]=c4r-u5r; Xi[5]=c4i-u5i;
    const float u7r=(c7i-c7r)*R2, u7i=-(c7r+c7i)*R2;       // w8^3 * c7
    Xr[3]=c6r+u7r; Xi[3]=c6i+u7i;
    Xr[7]=c6r-u7r; Xi[7]=c6i-u7i;
}

template<int S, int MI, int MO>
__device__ __forceinline__ void r8c_stage(const float2* __restrict__ x,
                                          float2* __restrict__ y,
                                          int t, const float2* __restrict__ Wc)
{
    const int p = t / S;
    const int q = t - p * S;
    float ar[8], ai[8];
    #pragma unroll
    for (int j = 0; j < 8; j++) {
        int m = t + 64 * j;
        if (MI) m = phi(m);
        const float2 v = x[m];
        ar[j] = v.x; ai[j] = v.y;
    }
    float Xr[8], Xi[8];
    r8_butterfly(ar, ai, Xr, Xi);

    if (S < 64) {   // twiddle chain from single table lookup W^{S*p} (e<=63)
        const float2 w1 = Wc[S * p];
        float wr = w1.x, wi = w1.y;
        #pragma unroll
        for (int k = 1; k < 8; k++) {
            const float tr = Xr[k]*wr - Xi[k]*wi;
            const float ti = Xr[k]*wi + Xi[k]*wr;
            Xr[k] = tr; Xi[k] = ti;
            const float nr = wr*w1.x - wi*w1.y;
            const float ni = wr*w1.y + wi*w1.x;
            wr = nr; wi = ni;
        }
    }
    #pragma unroll
    for (int k = 0; k < 8; k++) {
        int m = 8*S*p + q + S*k;
        if (MO) m = phi(m);
        y[m] = make_float2(Xr[k], Xi[k]);
    }
}

// Last inverse stage (S=64, no twiddle): registers -> global, coalesced.
// orows points at out + row_even*NB; row_odd = row_even+1 gets -Im.
__device__ __forceinline__ void r8c_last_inv(const float2* __restrict__ x,
                                             float* __restrict__ o_even,
                                             int t)
{
    float ar[8], ai[8];
    #pragma unroll
    for (int j = 0; j < 8; j++) {
        const float2 v = x[phi(t + 64 * j)];
        ar[j] = v.x; ai[j] = v.y;
    }
    float Xr[8], Xi[8];
    r8_butterfly(ar, ai, Xr, Xi);
    const float inv = 1.0f / 512.0f;
    float* o_odd = o_even + NB;
    #pragma unroll
    for (int k = 0; k < 8; k++) {
        o_even[t + 64 * k] =  Xr[k] * inv;
        o_odd [t + 64 * k] = -Xi[k] * inv;
    }
}

// ---------------------------------------------------------------------------
// Persistent main kernel. Per fetched group (4 rows): stage+gather (fwd
// inputs, cbuf0 slots 0-5), one 8-slot radix-8 wave (fwd slots 0-5 of this
// group + inverse slots 6-7 of previous group; inverse last stage streams
// to global), then spectral product writes next inverse inputs directly
// into cbuf0 slots 6-7 (Hermitian-extended conj(Pe + i*Po)).
// ---------------------------------------------------------------------------
#define OFF_PERM   0          // 33792 (3*5632 u16)
#define OFF_OFF    33792      // 3078 -> 3080
#define OFF_X      36872      // 32776 (4097 float2); cbuf1 aliases first 32768
#define OFF_BUF0   69648      // 32768 (float2[8][512])
#define OFF_W      102416     // 512: float2[64]
#define SMEM_BYTES 102928

__global__ void __launch_bounds__(NTHREADS, 2)
poly_sketch_kernel(const float* __restrict__ X, float* __restrict__ out)
{
    extern __shared__ char sm[];
    unsigned short* shPerm = (unsigned short*)(sm + OFF_PERM);
    unsigned short* shOff  = (unsigned short*)(sm + OFF_OFF);
    float2* shX2  = (float2*)(sm + OFF_X);
    float2* cbuf1 = (float2*)(sm + OFF_X);      // aliases shX2 (disjoint lifetime)
    float2* cbuf0 = (float2*)(sm + OFF_BUF0);
    float2* Wc    = (float2*)(sm + OFF_W);
    __shared__ int sh_g;

    const int tid = threadIdx.x;

    {   // load CSR
        const int* gp = (const int*)g_perm;
        int* sp = (int*)shPerm;
        #pragma unroll
        for (int i = tid; i < DEG * PSTRIDE / 2; i += NTHREADS) sp[i] = gp[i];
        for (int i = tid; i < DEG * (NB + 1); i += NTHREADS) shOff[i] = g_off[i];
    }
    if (tid < 64) {
        float ang = -6.283185307179586f * (float)tid * (1.0f / 512.0f);
        float s, c; sincosf(ang, &s, &c);
        Wc[tid] = make_float2(c, s);
    }
    if (tid == 0) shX2[4096] = make_float2(0.f, 0.f);  // pad slot
    __syncthreads();

    const int fftid = tid >> 6;
    const int t64 = tid & 63;
    int prev = -1;

    for (;;) {
        if (tid == 0) sh_g = (int)atomicAdd(&g_ctr, 1u);
        __syncthreads();
        const int g = sh_g;
        const bool have = (g < NGROUPS);
        if (!have && prev < 0) break;

        if (have) {
            const int grow = g * 4;
            #pragma unroll
            for (int pp = 0; pp < 2; pp++) {
                const int r0 = grow + 2 * pp;
                {   // stage X pair, interleaved float2, swizzled (conflict-free)
                    const float4* X0 = (const float4*)(X + (size_t)r0 * FDIM);
                    const float4* X1 = (const float4*)(X + (size_t)(r0 + 1) * FDIM);
                    #pragma unroll
                    for (int j = 0; j < (FDIM / 4) / NTHREADS; j++) {
                        const int f4 = j * NTHREADS + tid;
                        const float4 v0 = X0[f4];
                        const float4 v1 = X1[f4];
                        const int sidx = 4 * f4;
                        const int wz = (f4 >> 2) & 3;
                        shX2[sidx + (0 ^ wz)] = make_float2(v0.x, v1.x);
                        shX2[sidx + (1 ^ wz)] = make_float2(v0.y, v1.y);
                        shX2[sidx + (2 ^ wz)] = make_float2(v0.z, v1.z);
                        shX2[sidx + (3 ^ wz)] = make_float2(v0.w, v1.w);
                    }
                }
                __syncthreads();
                // gather count-sketch, both rows, 3 degrees -> cbuf0 slots 3pp+d
                #pragma unroll
                for (int d = 0; d < DEG; d++) {
                    const uint2* pm = (const uint2*)(shPerm + d * PSTRIDE);
                    const int s = shOff[d * (NB + 1) + tid];
                    const int e = shOff[d * (NB + 1) + tid + 1];
                    float a0 = 0.f, a1 = 0.f;
                    for (int qq = s; qq < e; qq++) {
                        const uint2 w = pm[qq];
                        const unsigned e0 = w.x & 0xffffu, e1 = w.x >> 16;
                        const unsigned e2 = w.y & 0xffffu, e3 = w.y >> 16;
                        const float2 x0 = shX2[e0 & 0x1fffu];   // pre-swizzled
                        const unsigned m0 = ((~e0) & 0x8000u) << 16;
                        a0 += __int_as_float(__float_as_int(x0.x) ^ m0);
                        a1 += __int_as_float(__float_as_int(x0.y) ^ m0);
                        const float2 x1 = shX2[e1 & 0x1fffu];
                        const unsigned m1 = ((~e1) & 0x8000u) << 16;
                        a0 += __int_as_float(__float_as_int(x1.x) ^ m1);
                        a1 += __int_as_float(__float_as_int(x1.y) ^ m1);
                        const float2 x2 = shX2[e2 & 0x1fffu];
                        const unsigned m2 = ((~e2) & 0x8000u) << 16;
                        a0 += __int_as_float(__float_as_int(x2.x) ^ m2);
                        a1 += __int_as_float(__float_as_int(x2.y) ^ m2);
                        const float2 x3 = shX2[e3 & 0x1fffu];
                        const unsigned m3 = ((~e3) & 0x8000u) << 16;
                        a0 += __int_as_float(__float_as_int(x3.x) ^ m3);
                        a1 += __int_as_float(__float_as_int(x3.y) ^ m3);
                    }
                    cbuf0[(pp * 3 + d) * 512 + tid] = make_float2(a0, a1);
                }
                __syncthreads();
            }
        }

        {   // 8-slot radix-8 FFT wave, named barrier per slot between stages
            const bool active = (fftid < 6) ? have : (prev >= 0);
            if (active) {
                const float2* b0 = cbuf0 + fftid * 512;
                float2*       b1 = cbuf1 + fftid * 512;
                r8c_stage<1, 0, 1>(b0, b1, t64, Wc);
                asm volatile("bar.sync %0, 64;" :: "r"(fftid + 1) : "memory");
                r8c_stage<8, 1, 1>(b1, (float2*)b0, t64, Wc);
                asm volatile("bar.sync %0, 64;" :: "r"(fftid + 1) : "memory");
                if (fftid < 6) {
                    r8c_stage<64, 1, 0>(b0, b1, t64, Wc);
                } else {
                    // inverse last stage: stream to global (rows prev*4 + 2s, +1)
                    float* o_even = out + ((size_t)prev * 4 + 2 * (fftid - 6)) * NB;
                    r8c_last_inv(b0, o_even, t64);
                }
            }
        }
        __syncthreads();

        if (have) {  // Hermitian split + 3-way product -> Q directly (slots 6,7)
            const int pp = tid >> 8;
            const int k0 = tid & 255;
            float2* Qs = cbuf0 + (6 + pp) * 512;
            const int nrep = (k0 == 0) ? 2 : 1;   // k0==0 also does k=256
            for (int rep = 0; rep < nrep; rep++) {
                const int k = rep ? 256 : k0;
                const int kr = (NB - k) & (NB - 1);
                float er = 1.f, ei = 0.f, odr = 1.f, odi = 0.f;
                #pragma unroll
                for (int d = 0; d < DEG; d++) {
                    const int slot = pp * 3 + d;
                    const float2 z = cbuf1[slot * 512 + k];
                    const float2 w = cbuf1[slot * 512 + kr];
                    const float ser = 0.5f * (z.x + w.x), sei = 0.5f * (z.y - w.y);
                    const float sor = 0.5f * (z.y + w.y), soi = 0.5f * (w.x - z.x);
                    float tr = er * ser - ei * sei;  ei = er * sei + ei * ser;  er = tr;
                    tr = odr * sor - odi * soi;      odi = odr * soi + odi * sor; odr = tr;
                }
                // Q = conj(Pe + i*Po), Hermitian-extended; write k and 512-k
                Qs[k]  = make_float2(er - odi, -(ei + odr));
                Qs[kr] = make_float2(er + odi, ei - odr);
            }
        }
        __syncthreads();
        prev = have ? g : -1;
    }
}

extern "C" void kernel_launch(void* const* d_in, const int* in_sizes, int n_in,
                              void* d_out, int out_size)
{
    const float* X  = (const float*)d_in[0];
    const int*   ih = (const int*)d_in[1];
    const int*   bh = (const int*)d_in[2];
    float* out = (float*)d_out;

    cudaFuncSetAttribute(poly_sketch_kernel,
                         cudaFuncAttributeMaxDynamicSharedMemorySize, SMEM_BYTES);
    build_csr<<<DEG, NTHREADS>>>(ih, bh);
    poly_sketch_kernel<<<GRID_MAIN, NTHREADS, SMEM_BYTES>>>(X, out);
}